// round 2
// baseline (speedup 1.0000x reference)
#include <cuda_runtime.h>
#include <cuda_bf16.h>
#include <math.h>

// Problem constants
#define BSZ   2
#define NPIX  65536           // H*W = 256*256
#define MROWS 131072          // B*N
#define TTEX  8192            // B*64*64
#define D1    1024
#define D2    512
#define D3    256
#define D4    128

// ---------------- static scratch (no runtime allocation allowed) ----------------
__device__ float g_hrT   [(size_t)MROWS * 128];   //  67 MB  hr_guide transposed [r,128]
__device__ float g_texT  [(size_t)TTEX  * 256];   // 8.4 MB  [feat | lr_guide] per texel
__device__ float g_Wsum  [128 * D1];              // W_g1 + W_g2
__device__ float g_WP    [256 * D1];              // [W_f ; -W_g2]
__device__ float g_hrproj[(size_t)MROWS * D1];    // 536 MB
__device__ float g_P     [(size_t)TTEX  * D1];    //  33 MB
__device__ float g_act1  [(size_t)MROWS * D1];    // 536 MB
__device__ float g_act2  [(size_t)MROWS * D2];    // 268 MB
__device__ float g_act3  [(size_t)MROWS * D3];    // 134 MB
__device__ float g_act4  [(size_t)MROWS * D4];    //  67 MB
__device__ float g_preds [(size_t)MROWS * 8];     //   4 MB  [r][corner][2]

// ---------------- packed fp32x2 helpers (Blackwell dual-FP32 pipe) ----------------
__device__ __forceinline__ unsigned long long pack2(float x) {
    unsigned long long r;
    asm("mov.b64 %0, {%1, %1};" : "=l"(r) : "f"(x));
    return r;
}
__device__ __forceinline__ void fma2(unsigned long long& d,
                                     unsigned long long a,
                                     unsigned long long b) {
    asm("fma.rn.f32x2 %0, %1, %2, %0;" : "+l"(d) : "l"(a), "l"(b));
}
__device__ __forceinline__ float lo32(unsigned long long v) {
    return __uint_as_float((unsigned)(v & 0xffffffffull));
}
__device__ __forceinline__ float hi32(unsigned long long v) {
    return __uint_as_float((unsigned)(v >> 32));
}

// ---------------- weight prep: Wsum = W_g1+W_g2 ; WP = [W_f ; -W_g2] ----------------
__global__ void prep_w_kernel(const float* __restrict__ w1) {
    int i = blockIdx.x * blockDim.x + threadIdx.x;   // 0 .. 256*1024-1
    if (i < 128 * D1) {
        g_Wsum[i] = w1[i + 128 * D1] + w1[i + 256 * D1];
    }
    if (i < 256 * D1) {
        int k = i >> 10;                 // row of WP
        if (k < 128) g_WP[i] = w1[i];                   // W_f rows 0..127
        else         g_WP[i] = -w1[i + 128 * D1];       // -W_g2 (w1 row k+128)
    }
}

// ---------------- channel-major -> row-major transpose ----------------
// in[k*NP + n] (per batch) -> out[n*outStride + outOff + k]
__global__ void transpose_cm_kernel(const float* __restrict__ in, float* __restrict__ out,
                                    int NP, long long inBatch, long long outBatch,
                                    int outStride, int outOff) {
    __shared__ float tile[32][33];
    int b = blockIdx.z;
    const float* inb = in + (long long)b * inBatch;
    float* outb = out + (long long)b * outBatch;
    int n0 = blockIdx.x * 32, k0 = blockIdx.y * 32;
    int tx = threadIdx.x, ty = threadIdx.y;
    tile[ty][tx] = inb[(long long)(k0 + ty) * NP + n0 + tx];
    __syncthreads();
    outb[(long long)(n0 + ty) * outStride + outOff + k0 + tx] = tile[tx][ty];
}

// ---------------- fp32x2 SGEMM: C[M,N] = (A[M,K] @ B[K,N]) + bias (opt relu) ----------------
#define GMB 128
#define GNB 128
#define GKB 16
__global__ __launch_bounds__(256)
void gemm_f32_kernel(const float* __restrict__ A, const float* __restrict__ Bw,
                     const float* __restrict__ bias, float* __restrict__ C,
                     int M, int N, int K, int doRelu) {
    __shared__ float As[2][GKB][GMB];   // A transposed in smem
    __shared__ float Bs[2][GKB][GNB];

    int tid = threadIdx.x;
    int tx = tid & 15;          // n sub-tile
    int ty = tid >> 4;          // m sub-tile
    int mBase = blockIdx.y * GMB;
    int nBase = blockIdx.x * GNB;

    unsigned long long acc[8][4];
#pragma unroll
    for (int i = 0; i < 8; i++)
#pragma unroll
        for (int j = 0; j < 4; j++) acc[i][j] = 0ull;

    int aRow  = tid >> 2;       // 0..63 (and +64)
    int aC4   = tid & 3;        // which float4 within the 16-wide k tile
    int bRowk = tid >> 5;       // 0..7  (and +8)
    int bC4   = tid & 31;       // which float4 within 128-wide n tile

    float4 ra0, ra1, rb0, rb1;

    // prologue: load k-tile 0
    ra0 = *(const float4*)(A + (long long)(mBase + aRow) * K + aC4 * 4);
    ra1 = *(const float4*)(A + (long long)(mBase + aRow + 64) * K + aC4 * 4);
    rb0 = *(const float4*)(Bw + (long long)(bRowk) * N + nBase + bC4 * 4);
    rb1 = *(const float4*)(Bw + (long long)(bRowk + 8) * N + nBase + bC4 * 4);
    {
        As[0][aC4 * 4 + 0][aRow] = ra0.x;
        As[0][aC4 * 4 + 1][aRow] = ra0.y;
        As[0][aC4 * 4 + 2][aRow] = ra0.z;
        As[0][aC4 * 4 + 3][aRow] = ra0.w;
        As[0][aC4 * 4 + 0][aRow + 64] = ra1.x;
        As[0][aC4 * 4 + 1][aRow + 64] = ra1.y;
        As[0][aC4 * 4 + 2][aRow + 64] = ra1.z;
        As[0][aC4 * 4 + 3][aRow + 64] = ra1.w;
        *(float4*)&Bs[0][bRowk][bC4 * 4] = rb0;
        *(float4*)&Bs[0][bRowk + 8][bC4 * 4] = rb1;
    }
    __syncthreads();

    int nk = K / GKB;
    for (int kt = 0; kt < nk; kt++) {
        int buf = kt & 1;
        if (kt + 1 < nk) {
            int k0 = (kt + 1) * GKB;
            ra0 = *(const float4*)(A + (long long)(mBase + aRow) * K + k0 + aC4 * 4);
            ra1 = *(const float4*)(A + (long long)(mBase + aRow + 64) * K + k0 + aC4 * 4);
            rb0 = *(const float4*)(Bw + (long long)(k0 + bRowk) * N + nBase + bC4 * 4);
            rb1 = *(const float4*)(Bw + (long long)(k0 + bRowk + 8) * N + nBase + bC4 * 4);
        }
#pragma unroll
        for (int k = 0; k < GKB; k++) {
            float4 a0 = *(const float4*)&As[buf][k][ty * 8];
            float4 a1 = *(const float4*)&As[buf][k][ty * 8 + 4];
            ulonglong2 bq0 = *(const ulonglong2*)&Bs[buf][k][tx * 8];
            ulonglong2 bq1 = *(const ulonglong2*)&Bs[buf][k][tx * 8 + 4];
            unsigned long long bq[4] = {bq0.x, bq0.y, bq1.x, bq1.y};
            float am[8] = {a0.x, a0.y, a0.z, a0.w, a1.x, a1.y, a1.z, a1.w};
#pragma unroll
            for (int m = 0; m < 8; m++) {
                unsigned long long ap = pack2(am[m]);
                fma2(acc[m][0], ap, bq[0]);
                fma2(acc[m][1], ap, bq[1]);
                fma2(acc[m][2], ap, bq[2]);
                fma2(acc[m][3], ap, bq[3]);
            }
        }
        if (kt + 1 < nk) {
            int nb = buf ^ 1;
            As[nb][aC4 * 4 + 0][aRow] = ra0.x;
            As[nb][aC4 * 4 + 1][aRow] = ra0.y;
            As[nb][aC4 * 4 + 2][aRow] = ra0.z;
            As[nb][aC4 * 4 + 3][aRow] = ra0.w;
            As[nb][aC4 * 4 + 0][aRow + 64] = ra1.x;
            As[nb][aC4 * 4 + 1][aRow + 64] = ra1.y;
            As[nb][aC4 * 4 + 2][aRow + 64] = ra1.z;
            As[nb][aC4 * 4 + 3][aRow + 64] = ra1.w;
            *(float4*)&Bs[nb][bRowk][bC4 * 4] = rb0;
            *(float4*)&Bs[nb][bRowk + 8][bC4 * 4] = rb1;
        }
        __syncthreads();
    }

    // epilogue
#pragma unroll
    for (int m = 0; m < 8; m++) {
        int row = mBase + ty * 8 + m;
        int col = nBase + tx * 8;
        float v[8];
#pragma unroll
        for (int j = 0; j < 4; j++) {
            v[2 * j]     = lo32(acc[m][j]);
            v[2 * j + 1] = hi32(acc[m][j]);
        }
        if (bias) {
#pragma unroll
            for (int j = 0; j < 8; j++) v[j] += bias[col + j];
        }
        if (doRelu) {
#pragma unroll
            for (int j = 0; j < 8; j++) v[j] = fmaxf(v[j], 0.0f);
        }
        *(float4*)(C + (long long)row * N + col)     = make_float4(v[0], v[1], v[2], v[3]);
        *(float4*)(C + (long long)row * N + col + 4) = make_float4(v[4], v[5], v[6], v[7]);
    }
}

// ---------------- per-corner layer-1 assembly ----------------
// act1[r,:] = relu( hr_proj[r,:] + valid*P[t,:] + ry*Wd0 + rx*Wd1 )
__global__ __launch_bounds__(256)
void assemble_kernel(const float* __restrict__ coord, const float* __restrict__ w1,
                     float vx, float vy) {
    int r = blockIdx.x;
    int b = r >> 16;
    float c0 = coord[(long long)r * 2 + 0];
    float c1 = coord[(long long)r * 2 + 1];
    float cy = c0 + vx * 0.015625f;       // vx * (1/h)
    float cx = c1 + vy * 0.015625f;       // vy * (1/w)
    // replicate reference fp32 ops exactly
    float fy = (cy + 1.0f) * 64.0f / 2.0f - 0.5f;
    float fx = (cx + 1.0f) * 64.0f / 2.0f - 0.5f;
    int iy = (int)floorf(fy + 0.5f);
    int ix = (int)floorf(fx + 0.5f);
    bool valid = (iy >= 0 && iy < 64 && ix >= 0 && ix < 64);
    int iyc = min(max(iy, 0), 63);
    int ixc = min(max(ix, 0), 63);
    int t = b * 4096 + iyc * 64 + ixc;
    float ry, rx2;
    if (valid) {
        float cenY = -1.0f + 0.015625f + 0.03125f * (float)iyc;
        float cenX = -1.0f + 0.015625f + 0.03125f * (float)ixc;
        ry  = (c0 - cenY) * 64.0f;
        rx2 = (c1 - cenX) * 64.0f;
    } else {
        ry  = c0 * 64.0f;   // q_coord sampled as zeros
        rx2 = c1 * 64.0f;
    }
    float vm = valid ? 1.0f : 0.0f;

    int k = threadIdx.x * 4;
    float4 hp  = *(const float4*)&g_hrproj[(long long)r * D1 + k];
    float4 pp  = *(const float4*)&g_P[(long long)t * D1 + k];
    float4 wd0 = *(const float4*)&w1[384 * D1 + k];
    float4 wd1 = *(const float4*)&w1[385 * D1 + k];
    float4 o;
    o.x = fmaxf(hp.x + vm * pp.x + ry * wd0.x + rx2 * wd1.x, 0.0f);
    o.y = fmaxf(hp.y + vm * pp.y + ry * wd0.y + rx2 * wd1.y, 0.0f);
    o.z = fmaxf(hp.z + vm * pp.z + ry * wd0.z + rx2 * wd1.z, 0.0f);
    o.w = fmaxf(hp.w + vm * pp.w + ry * wd0.w + rx2 * wd1.w, 0.0f);
    *(float4*)&g_act1[(long long)r * D1 + k] = o;
}

// ---------------- layer 5: [131072,128] @ [128,2] + b5 -> preds ----------------
__global__ __launch_bounds__(256)
void final5_kernel(const float* __restrict__ w5, const float* __restrict__ b5, int corner) {
    int warp = (blockIdx.x * blockDim.x + threadIdx.x) >> 5;
    int lane = threadIdx.x & 31;
    if (warp >= MROWS) return;
    const float* a = &g_act4[(long long)warp * D4];
    float s0 = 0.0f, s1 = 0.0f;
#pragma unroll
    for (int i = lane; i < 128; i += 32) {
        float av = a[i];
        s0 += av * w5[i * 2 + 0];
        s1 += av * w5[i * 2 + 1];
    }
#pragma unroll
    for (int off = 16; off > 0; off >>= 1) {
        s0 += __shfl_xor_sync(0xffffffffu, s0, off);
        s1 += __shfl_xor_sync(0xffffffffu, s1, off);
    }
    if (lane == 0) {
        g_preds[(long long)warp * 8 + corner * 2 + 0] = s0 + b5[0];
        g_preds[(long long)warp * 8 + corner * 2 + 1] = s1 + b5[1];
    }
}

// ---------------- softmax blend over 4 corners ----------------
__global__ __launch_bounds__(256)
void reduce_kernel(float* __restrict__ out) {
    int r = blockIdx.x * blockDim.x + threadIdx.x;
    if (r >= MROWS) return;
    float p0[4], p1[4];
#pragma unroll
    for (int c = 0; c < 4; c++) {
        p0[c] = g_preds[(long long)r * 8 + c * 2 + 0];
        p1[c] = g_preds[(long long)r * 8 + c * 2 + 1];
    }
    float m = fmaxf(fmaxf(p1[0], p1[1]), fmaxf(p1[2], p1[3]));
    float se = 0.0f, num = 0.0f;
#pragma unroll
    for (int c = 0; c < 4; c++) {
        float e = expf(p1[c] - m);
        se += e;
        num += p0[c] * e;
    }
    out[r] = num / se;
}

// ---------------- launch ----------------
extern "C" void kernel_launch(void* const* d_in, const int* in_sizes, int n_in,
                              void* d_out, int out_size) {
    const float* feat  = (const float*)d_in[0];
    const float* coord = (const float*)d_in[1];
    const float* hrg   = (const float*)d_in[2];
    const float* lrg   = (const float*)d_in[3];
    const float* w1 = (const float*)d_in[4];
    const float* b1 = (const float*)d_in[5];
    const float* w2 = (const float*)d_in[6];
    const float* b2 = (const float*)d_in[7];
    const float* w3 = (const float*)d_in[8];
    const float* b3 = (const float*)d_in[9];
    const float* w4 = (const float*)d_in[10];
    const float* b4 = (const float*)d_in[11];
    const float* w5 = (const float*)d_in[12];
    const float* b5 = (const float*)d_in[13];
    float* out = (float*)d_out;

    float *p_hrT, *p_texT, *p_Wsum, *p_WP, *p_hrproj, *p_P, *p_act1, *p_act2, *p_act3, *p_act4;
    cudaGetSymbolAddress((void**)&p_hrT, g_hrT);
    cudaGetSymbolAddress((void**)&p_texT, g_texT);
    cudaGetSymbolAddress((void**)&p_Wsum, g_Wsum);
    cudaGetSymbolAddress((void**)&p_WP, g_WP);
    cudaGetSymbolAddress((void**)&p_hrproj, g_hrproj);
    cudaGetSymbolAddress((void**)&p_P, g_P);
    cudaGetSymbolAddress((void**)&p_act1, g_act1);
    cudaGetSymbolAddress((void**)&p_act2, g_act2);
    cudaGetSymbolAddress((void**)&p_act3, g_act3);
    cudaGetSymbolAddress((void**)&p_act4, g_act4);

    // weight prep
    prep_w_kernel<<<1024, 256>>>(w1);

    // transposes: channel-major -> row-major
    dim3 tb(32, 32);
    // hr_guide [B,128,65536] -> g_hrT [B*65536, 128]
    transpose_cm_kernel<<<dim3(65536 / 32, 128 / 32, BSZ), tb>>>(
        hrg, p_hrT, 65536, 128LL * 65536, 65536LL * 128, 128, 0);
    // feat [B,128,4096] -> g_texT[:, 0:128]
    transpose_cm_kernel<<<dim3(4096 / 32, 128 / 32, BSZ), tb>>>(
        feat, p_texT, 4096, 128LL * 4096, 4096LL * 256, 256, 0);
    // lr_guide [B,128,4096] -> g_texT[:, 128:256]
    transpose_cm_kernel<<<dim3(4096 / 32, 128 / 32, BSZ), tb>>>(
        lrg, p_texT, 4096, 128LL * 4096, 4096LL * 256, 256, 128);

    // hr_proj = hrT @ Wsum + b1      [131072, 1024]
    gemm_f32_kernel<<<dim3(D1 / GNB, MROWS / GMB), 256>>>(
        p_hrT, p_Wsum, b1, p_hrproj, MROWS, D1, 128, 0);
    // P = texT @ WP                  [8192, 1024]
    gemm_f32_kernel<<<dim3(D1 / GNB, TTEX / GMB), 256>>>(
        p_texT, p_WP, (const float*)0, p_P, TTEX, D1, 256, 0);

    const float vxs[4] = {-1.0f, -1.0f, 1.0f, 1.0f};
    const float vys[4] = {-1.0f, 1.0f, -1.0f, 1.0f};
    for (int c = 0; c < 4; c++) {
        assemble_kernel<<<MROWS, 256>>>(coord, w1, vxs[c], vys[c]);
        gemm_f32_kernel<<<dim3(D2 / GNB, MROWS / GMB), 256>>>(
            p_act1, w2, b2, p_act2, MROWS, D2, D1, 1);
        gemm_f32_kernel<<<dim3(D3 / GNB, MROWS / GMB), 256>>>(
            p_act2, w3, b3, p_act3, MROWS, D3, D2, 1);
        gemm_f32_kernel<<<dim3(D4 / GNB, MROWS / GMB), 256>>>(
            p_act3, w4, b4, p_act4, MROWS, D4, D3, 1);
        final5_kernel<<<MROWS / 8, 256>>>(w5, b5, c);
    }
    reduce_kernel<<<MROWS / 256, 256>>>(out);
}

// round 5
// speedup vs baseline: 1.0005x; 1.0005x over previous
#include <cuda_runtime.h>
#include <cuda_bf16.h>
#include <math.h>

// Problem constants
#define BSZ   2
#define NPIX  65536           // H*W = 256*256
#define MROWS 131072          // B*N
#define TTEX  8192            // B*64*64
#define D1    1024
#define D2    512
#define D3    256
#define D4    128

// ---------------- static scratch (no runtime allocation allowed) ----------------
__device__ float g_hrT   [(size_t)MROWS * 128];   //  67 MB  hr_guide transposed [r,128]
__device__ float g_texT  [(size_t)TTEX  * 256];   // 8.4 MB  [feat | lr_guide] per texel
__device__ float g_Wsum  [128 * D1];              // W_g1 + W_g2
__device__ float g_WP    [256 * D1];              // [W_f ; -W_g2]
__device__ float g_hrproj[(size_t)MROWS * D1];    // 536 MB
__device__ float g_P     [(size_t)TTEX  * D1];    //  33 MB
__device__ float g_act1  [(size_t)MROWS * D1];    // 536 MB
__device__ float g_act2  [(size_t)MROWS * D2];    // 268 MB
__device__ float g_act3  [(size_t)MROWS * D3];    // 134 MB
__device__ float g_act4  [(size_t)MROWS * D4];    //  67 MB
__device__ float g_preds [(size_t)MROWS * 8];     //   4 MB  [r][corner][2]

// ---------------- packed fp32x2 helpers (Blackwell dual-FP32 pipe) ----------------
__device__ __forceinline__ unsigned long long pack2(float x) {
    unsigned long long r;
    asm("mov.b64 %0, {%1, %1};" : "=l"(r) : "f"(x));
    return r;
}
__device__ __forceinline__ void fma2(unsigned long long& d,
                                     unsigned long long a,
                                     unsigned long long b) {
    asm("fma.rn.f32x2 %0, %1, %2, %0;" : "+l"(d) : "l"(a), "l"(b));
}
__device__ __forceinline__ float lo32(unsigned long long v) {
    return __uint_as_float((unsigned)(v & 0xffffffffull));
}
__device__ __forceinline__ float hi32(unsigned long long v) {
    return __uint_as_float((unsigned)(v >> 32));
}

// ---------------- weight prep: Wsum = W_g1+W_g2 ; WP = [W_f ; -W_g2] ----------------
__global__ void prep_w_kernel(const float* __restrict__ w1) {
    int i = blockIdx.x * blockDim.x + threadIdx.x;   // 0 .. 256*1024-1
    if (i < 128 * D1) {
        g_Wsum[i] = w1[i + 128 * D1] + w1[i + 256 * D1];
    }
    if (i < 256 * D1) {
        int k = i >> 10;                 // row of WP
        if (k < 128) g_WP[i] = w1[i];                   // W_f rows 0..127
        else         g_WP[i] = -w1[i + 128 * D1];       // -W_g2 (w1 row k+128)
    }
}

// ---------------- channel-major -> row-major transpose ----------------
// in[k*NP + n] (per batch) -> out[n*outStride + outOff + k]
__global__ void transpose_cm_kernel(const float* __restrict__ in, float* __restrict__ out,
                                    int NP, long long inBatch, long long outBatch,
                                    int outStride, int outOff) {
    __shared__ float tile[32][33];
    int b = blockIdx.z;
    const float* inb = in + (long long)b * inBatch;
    float* outb = out + (long long)b * outBatch;
    int n0 = blockIdx.x * 32, k0 = blockIdx.y * 32;
    int tx = threadIdx.x, ty = threadIdx.y;
    tile[ty][tx] = inb[(long long)(k0 + ty) * NP + n0 + tx];
    __syncthreads();
    outb[(long long)(n0 + ty) * outStride + outOff + k0 + tx] = tile[tx][ty];
}

// ---------------- fp32x2 SGEMM: C[M,N] = (A[M,K] @ B[K,N]) + bias (opt relu) ----------------
#define GMB 128
#define GNB 128
#define GKB 16
__global__ __launch_bounds__(256)
void gemm_f32_kernel(const float* __restrict__ A, const float* __restrict__ Bw,
                     const float* __restrict__ bias, float* __restrict__ C,
                     int M, int N, int K, int doRelu) {
    __shared__ float As[2][GKB][GMB];   // A transposed in smem
    __shared__ float Bs[2][GKB][GNB];

    int tid = threadIdx.x;
    int tx = tid & 15;          // n sub-tile
    int ty = tid >> 4;          // m sub-tile
    int mBase = blockIdx.y * GMB;
    int nBase = blockIdx.x * GNB;

    unsigned long long acc[8][4];
#pragma unroll
    for (int i = 0; i < 8; i++)
#pragma unroll
        for (int j = 0; j < 4; j++) acc[i][j] = 0ull;

    int aRow  = tid >> 2;       // 0..63 (and +64)
    int aC4   = tid & 3;        // which float4 within the 16-wide k tile
    int bRowk = tid >> 5;       // 0..7  (and +8)
    int bC4   = tid & 31;       // which float4 within 128-wide n tile

    float4 ra0, ra1, rb0, rb1;

    // prologue: load k-tile 0
    ra0 = *(const float4*)(A + (long long)(mBase + aRow) * K + aC4 * 4);
    ra1 = *(const float4*)(A + (long long)(mBase + aRow + 64) * K + aC4 * 4);
    rb0 = *(const float4*)(Bw + (long long)(bRowk) * N + nBase + bC4 * 4);
    rb1 = *(const float4*)(Bw + (long long)(bRowk + 8) * N + nBase + bC4 * 4);
    {
        As[0][aC4 * 4 + 0][aRow] = ra0.x;
        As[0][aC4 * 4 + 1][aRow] = ra0.y;
        As[0][aC4 * 4 + 2][aRow] = ra0.z;
        As[0][aC4 * 4 + 3][aRow] = ra0.w;
        As[0][aC4 * 4 + 0][aRow + 64] = ra1.x;
        As[0][aC4 * 4 + 1][aRow + 64] = ra1.y;
        As[0][aC4 * 4 + 2][aRow + 64] = ra1.z;
        As[0][aC4 * 4 + 3][aRow + 64] = ra1.w;
        *(float4*)&Bs[0][bRowk][bC4 * 4] = rb0;
        *(float4*)&Bs[0][bRowk + 8][bC4 * 4] = rb1;
    }
    __syncthreads();

    int nk = K / GKB;
    for (int kt = 0; kt < nk; kt++) {
        int buf = kt & 1;
        if (kt + 1 < nk) {
            int k0 = (kt + 1) * GKB;
            ra0 = *(const float4*)(A + (long long)(mBase + aRow) * K + k0 + aC4 * 4);
            ra1 = *(const float4*)(A + (long long)(mBase + aRow + 64) * K + k0 + aC4 * 4);
            rb0 = *(const float4*)(Bw + (long long)(k0 + bRowk) * N + nBase + bC4 * 4);
            rb1 = *(const float4*)(Bw + (long long)(k0 + bRowk + 8) * N + nBase + bC4 * 4);
        }
#pragma unroll
        for (int k = 0; k < GKB; k++) {
            float4 a0 = *(const float4*)&As[buf][k][ty * 8];
            float4 a1 = *(const float4*)&As[buf][k][ty * 8 + 4];
            ulonglong2 bq0 = *(const ulonglong2*)&Bs[buf][k][tx * 8];
            ulonglong2 bq1 = *(const ulonglong2*)&Bs[buf][k][tx * 8 + 4];
            unsigned long long bq[4] = {bq0.x, bq0.y, bq1.x, bq1.y};
            float am[8] = {a0.x, a0.y, a0.z, a0.w, a1.x, a1.y, a1.z, a1.w};
#pragma unroll
            for (int m = 0; m < 8; m++) {
                unsigned long long ap = pack2(am[m]);
                fma2(acc[m][0], ap, bq[0]);
                fma2(acc[m][1], ap, bq[1]);
                fma2(acc[m][2], ap, bq[2]);
                fma2(acc[m][3], ap, bq[3]);
            }
        }
        if (kt + 1 < nk) {
            int nb = buf ^ 1;
            As[nb][aC4 * 4 + 0][aRow] = ra0.x;
            As[nb][aC4 * 4 + 1][aRow] = ra0.y;
            As[nb][aC4 * 4 + 2][aRow] = ra0.z;
            As[nb][aC4 * 4 + 3][aRow] = ra0.w;
            As[nb][aC4 * 4 + 0][aRow + 64] = ra1.x;
            As[nb][aC4 * 4 + 1][aRow + 64] = ra1.y;
            As[nb][aC4 * 4 + 2][aRow + 64] = ra1.z;
            As[nb][aC4 * 4 + 3][aRow + 64] = ra1.w;
            *(float4*)&Bs[nb][bRowk][bC4 * 4] = rb0;
            *(float4*)&Bs[nb][bRowk + 8][bC4 * 4] = rb1;
        }
        __syncthreads();
    }

    // epilogue
#pragma unroll
    for (int m = 0; m < 8; m++) {
        int row = mBase + ty * 8 + m;
        int col = nBase + tx * 8;
        float v[8];
#pragma unroll
        for (int j = 0; j < 4; j++) {
            v[2 * j]     = lo32(acc[m][j]);
            v[2 * j + 1] = hi32(acc[m][j]);
        }
        if (bias) {
#pragma unroll
            for (int j = 0; j < 8; j++) v[j] += bias[col + j];
        }
        if (doRelu) {
#pragma unroll
            for (int j = 0; j < 8; j++) v[j] = fmaxf(v[j], 0.0f);
        }
        *(float4*)(C + (long long)row * N + col)     = make_float4(v[0], v[1], v[2], v[3]);
        *(float4*)(C + (long long)row * N + col + 4) = make_float4(v[4], v[5], v[6], v[7]);
    }
}

// ---------------- per-corner layer-1 assembly ----------------
// act1[r,:] = relu( hr_proj[r,:] + valid*P[t,:] + ry*Wd0 + rx*Wd1 )
__global__ __launch_bounds__(256)
void assemble_kernel(const float* __restrict__ coord, const float* __restrict__ w1,
                     float vx, float vy) {
    int r = blockIdx.x;
    int b = r >> 16;
    float c0 = coord[(long long)r * 2 + 0];
    float c1 = coord[(long long)r * 2 + 1];
    float cy = c0 + vx * 0.015625f;       // vx * (1/h)
    float cx = c1 + vy * 0.015625f;       // vy * (1/w)
    // replicate reference fp32 ops exactly
    float fy = (cy + 1.0f) * 64.0f / 2.0f - 0.5f;
    float fx = (cx + 1.0f) * 64.0f / 2.0f - 0.5f;
    int iy = (int)floorf(fy + 0.5f);
    int ix = (int)floorf(fx + 0.5f);
    bool valid = (iy >= 0 && iy < 64 && ix >= 0 && ix < 64);
    int iyc = min(max(iy, 0), 63);
    int ixc = min(max(ix, 0), 63);
    int t = b * 4096 + iyc * 64 + ixc;
    float ry, rx2;
    if (valid) {
        float cenY = -1.0f + 0.015625f + 0.03125f * (float)iyc;
        float cenX = -1.0f + 0.015625f + 0.03125f * (float)ixc;
        ry  = (c0 - cenY) * 64.0f;
        rx2 = (c1 - cenX) * 64.0f;
    } else {
        ry  = c0 * 64.0f;   // q_coord sampled as zeros
        rx2 = c1 * 64.0f;
    }
    float vm = valid ? 1.0f : 0.0f;

    int k = threadIdx.x * 4;
    float4 hp  = *(const float4*)&g_hrproj[(long long)r * D1 + k];
    float4 pp  = *(const float4*)&g_P[(long long)t * D1 + k];
    float4 wd0 = *(const float4*)&w1[384 * D1 + k];
    float4 wd1 = *(const float4*)&w1[385 * D1 + k];
    float4 o;
    o.x = fmaxf(hp.x + vm * pp.x + ry * wd0.x + rx2 * wd1.x, 0.0f);
    o.y = fmaxf(hp.y + vm * pp.y + ry * wd0.y + rx2 * wd1.y, 0.0f);
    o.z = fmaxf(hp.z + vm * pp.z + ry * wd0.z + rx2 * wd1.z, 0.0f);
    o.w = fmaxf(hp.w + vm * pp.w + ry * wd0.w + rx2 * wd1.w, 0.0f);
    *(float4*)&g_act1[(long long)r * D1 + k] = o;
}

// ---------------- layer 5: [131072,128] @ [128,2] + b5 -> preds ----------------
__global__ __launch_bounds__(256)
void final5_kernel(const float* __restrict__ w5, const float* __restrict__ b5, int corner) {
    int warp = (blockIdx.x * blockDim.x + threadIdx.x) >> 5;
    int lane = threadIdx.x & 31;
    if (warp >= MROWS) return;
    const float* a = &g_act4[(long long)warp * D4];
    float s0 = 0.0f, s1 = 0.0f;
#pragma unroll
    for (int i = lane; i < 128; i += 32) {
        float av = a[i];
        s0 += av * w5[i * 2 + 0];
        s1 += av * w5[i * 2 + 1];
    }
#pragma unroll
    for (int off = 16; off > 0; off >>= 1) {
        s0 += __shfl_xor_sync(0xffffffffu, s0, off);
        s1 += __shfl_xor_sync(0xffffffffu, s1, off);
    }
    if (lane == 0) {
        g_preds[(long long)warp * 8 + corner * 2 + 0] = s0 + b5[0];
        g_preds[(long long)warp * 8 + corner * 2 + 1] = s1 + b5[1];
    }
}

// ---------------- softmax blend over 4 corners ----------------
__global__ __launch_bounds__(256)
void reduce_kernel(float* __restrict__ out) {
    int r = blockIdx.x * blockDim.x + threadIdx.x;
    if (r >= MROWS) return;
    float p0[4], p1[4];
#pragma unroll
    for (int c = 0; c < 4; c++) {
        p0[c] = g_preds[(long long)r * 8 + c * 2 + 0];
        p1[c] = g_preds[(long long)r * 8 + c * 2 + 1];
    }
    float m = fmaxf(fmaxf(p1[0], p1[1]), fmaxf(p1[2], p1[3]));
    float se = 0.0f, num = 0.0f;
#pragma unroll
    for (int c = 0; c < 4; c++) {
        float e = expf(p1[c] - m);
        se += e;
        num += p0[c] * e;
    }
    out[r] = num / se;
}

// ---------------- launch ----------------
extern "C" void kernel_launch(void* const* d_in, const int* in_sizes, int n_in,
                              void* d_out, int out_size) {
    const float* feat  = (const float*)d_in[0];
    const float* coord = (const float*)d_in[1];
    const float* hrg   = (const float*)d_in[2];
    const float* lrg   = (const float*)d_in[3];
    const float* w1 = (const float*)d_in[4];
    const float* b1 = (const float*)d_in[5];
    const float* w2 = (const float*)d_in[6];
    const float* b2 = (const float*)d_in[7];
    const float* w3 = (const float*)d_in[8];
    const float* b3 = (const float*)d_in[9];
    const float* w4 = (const float*)d_in[10];
    const float* b4 = (const float*)d_in[11];
    const float* w5 = (const float*)d_in[12];
    const float* b5 = (const float*)d_in[13];
    float* out = (float*)d_out;

    float *p_hrT, *p_texT, *p_Wsum, *p_WP, *p_hrproj, *p_P, *p_act1, *p_act2, *p_act3, *p_act4;
    cudaGetSymbolAddress((void**)&p_hrT, g_hrT);
    cudaGetSymbolAddress((void**)&p_texT, g_texT);
    cudaGetSymbolAddress((void**)&p_Wsum, g_Wsum);
    cudaGetSymbolAddress((void**)&p_WP, g_WP);
    cudaGetSymbolAddress((void**)&p_hrproj, g_hrproj);
    cudaGetSymbolAddress((void**)&p_P, g_P);
    cudaGetSymbolAddress((void**)&p_act1, g_act1);
    cudaGetSymbolAddress((void**)&p_act2, g_act2);
    cudaGetSymbolAddress((void**)&p_act3, g_act3);
    cudaGetSymbolAddress((void**)&p_act4, g_act4);

    // weight prep
    prep_w_kernel<<<1024, 256>>>(w1);

    // transposes: channel-major -> row-major
    dim3 tb(32, 32);
    // hr_guide [B,128,65536] -> g_hrT [B*65536, 128]
    transpose_cm_kernel<<<dim3(65536 / 32, 128 / 32, BSZ), tb>>>(
        hrg, p_hrT, 65536, 128LL * 65536, 65536LL * 128, 128, 0);
    // feat [B,128,4096] -> g_texT[:, 0:128]
    transpose_cm_kernel<<<dim3(4096 / 32, 128 / 32, BSZ), tb>>>(
        feat, p_texT, 4096, 128LL * 4096, 4096LL * 256, 256, 0);
    // lr_guide [B,128,4096] -> g_texT[:, 128:256]
    transpose_cm_kernel<<<dim3(4096 / 32, 128 / 32, BSZ), tb>>>(
        lrg, p_texT, 4096, 128LL * 4096, 4096LL * 256, 256, 128);

    // hr_proj = hrT @ Wsum + b1      [131072, 1024]
    gemm_f32_kernel<<<dim3(D1 / GNB, MROWS / GMB), 256>>>(
        p_hrT, p_Wsum, b1, p_hrproj, MROWS, D1, 128, 0);
    // P = texT @ WP                  [8192, 1024]
    gemm_f32_kernel<<<dim3(D1 / GNB, TTEX / GMB), 256>>>(
        p_texT, p_WP, (const float*)0, p_P, TTEX, D1, 256, 0);

    const float vxs[4] = {-1.0f, -1.0f, 1.0f, 1.0f};
    const float vys[4] = {-1.0f, 1.0f, -1.0f, 1.0f};
    for (int c = 0; c < 4; c++) {
        assemble_kernel<<<MROWS, 256>>>(coord, w1, vxs[c], vys[c]);
        gemm_f32_kernel<<<dim3(D2 / GNB, MROWS / GMB), 256>>>(
            p_act1, w2, b2, p_act2, MROWS, D2, D1, 1);
        gemm_f32_kernel<<<dim3(D3 / GNB, MROWS / GMB), 256>>>(
            p_act2, w3, b3, p_act3, MROWS, D3, D2, 1);
        gemm_f32_kernel<<<dim3(D4 / GNB, MROWS / GMB), 256>>>(
            p_act3, w4, b4, p_act4, MROWS, D4, D3, 1);
        final5_kernel<<<MROWS / 8, 256>>>(w5, b5, c);
    }
    reduce_kernel<<<MROWS / 256, 256>>>(out);
}

// round 16
// speedup vs baseline: 1.8217x; 1.8208x over previous
#include <cuda_runtime.h>
#include <cuda_bf16.h>
#include <mma.h>
#include <cstdint>
#include <math.h>

using namespace nvcuda;

#define MROWS 131072
#define TTEX  8192

// ---------------- static scratch ----------------
__device__ __align__(256) __nv_bfloat16 g_hrT [(size_t)MROWS * 256];   // [r][hi128|lo128]
__device__ __align__(256) __nv_bfloat16 g_texT[(size_t)TTEX  * 512];   // [t][hi256|lo256]
__device__ __align__(256) __nv_bfloat16 g_Wsum[1024 * 256];            // [n][hi128|lo128]
__device__ __align__(256) __nv_bfloat16 g_WPt [1024 * 512];            // [n][hi256|lo256]
__device__ __align__(256) __nv_bfloat16 g_W2t [512 * 2048];            // [n][hi1024|lo1024]
__device__ __align__(256) __nv_bfloat16 g_W3t [256 * 1024];
__device__ __align__(256) __nv_bfloat16 g_W4t [128 * 512];
__device__ __align__(256) float g_hrproj[(size_t)MROWS * 1024];
__device__ __align__(256) float g_P     [(size_t)TTEX  * 1024];
__device__ __align__(256) __nv_bfloat16 g_act1[(size_t)MROWS * 2048];
__device__ __align__(256) __nv_bfloat16 g_act2[(size_t)MROWS * 1024];
__device__ __align__(256) __nv_bfloat16 g_act3[(size_t)MROWS * 512];
__device__ __align__(256) __nv_bfloat16 g_act4[(size_t)MROWS * 256];
__device__ float g_preds[(size_t)MROWS * 8];

__device__ __forceinline__ void split_store(__nv_bfloat16* hi, __nv_bfloat16* lo, float v) {
    __nv_bfloat16 h = __float2bfloat16(v);
    *hi = h;
    *lo = __float2bfloat16(v - __bfloat162float(h));
}

// ================= split-bf16 WMMA GEMM =================
// A: [M][2K] bf16 (hi K | lo K per row), B: [N][2K] bf16 same layout. C = A @ B^T.
// OM=0: fp32 out [M][Nfull].  OM=1: ReLU + split-bf16 out: hi at [r][c], lo at [r][Nfull+c].
// CTA tile 128x128, K-chunk 32, 256 threads = 8 warps of 64x32.
#define KC 32
#define ASTRIDE 40   // bf16 elements per smem row (32 + 8 pad)
#define STAGEB 40960u // bytes: 2 buf * 2 comp * 128 rows * 40 elem * 2B

template <int OM>
__global__ __launch_bounds__(256)
void gemm_wmma(const __nv_bfloat16* __restrict__ A,
               const __nv_bfloat16* __restrict__ B, int K, int Nfull,
               const float* __restrict__ bias, void* __restrict__ Cout) {
    extern __shared__ char sm[];
    const int tid = threadIdx.x, wid = tid >> 5;
    const int wr = wid >> 2, wc = wid & 3;           // warp tile: m = wr*64, n = wc*32
    const int mBase = blockIdx.y * 128, nBase = blockIdx.x * 128;
    const int ld = 2 * K;

    auto As = [&](int buf, int comp) {
        return (__nv_bfloat16*)sm + (size_t)(buf * 2 + comp) * 128 * ASTRIDE;
    };
    auto Bs = [&](int buf, int comp) {
        return (__nv_bfloat16*)(sm + STAGEB) + (size_t)(buf * 2 + comp) * 128 * ASTRIDE;
    };

    wmma::fragment<wmma::accumulator, 16, 16, 16, float> acc[4][2];
#pragma unroll
    for (int mf = 0; mf < 4; mf++)
#pragma unroll
        for (int nf = 0; nf < 2; nf++) wmma::fill_fragment(acc[mf][nf], 0.0f);

    const int nk = K / KC;
    uint4 ra[4], rb[4];

    // decode load slots: 4 A items + 4 B items per thread per chunk
    int rowA[4], compA[4], segA[4];
#pragma unroll
    for (int t = 0; t < 4; t++) {
        int idx = tid + t * 256;         // 0..1023
        rowA[t] = idx >> 3;
        compA[t] = (idx >> 2) & 1;
        segA[t] = idx & 3;
    }

    auto gload = [&](int kc) {
#pragma unroll
        for (int t = 0; t < 4; t++) {
            ra[t] = *(const uint4*)(A + (size_t)(mBase + rowA[t]) * ld +
                                    (size_t)compA[t] * K + kc + segA[t] * 8);
            rb[t] = *(const uint4*)(B + (size_t)(nBase + rowA[t]) * ld +
                                    (size_t)compA[t] * K + kc + segA[t] * 8);
        }
    };
    auto sstore = [&](int buf) {
#pragma unroll
        for (int t = 0; t < 4; t++) {
            *(uint4*)(As(buf, compA[t]) + rowA[t] * ASTRIDE + segA[t] * 8) = ra[t];
            *(uint4*)(Bs(buf, compA[t]) + rowA[t] * ASTRIDE + segA[t] * 8) = rb[t];
        }
    };

    gload(0);
    sstore(0);
    __syncthreads();

    for (int i = 0; i < nk; i++) {
        int buf = i & 1;
        if (i + 1 < nk) gload((i + 1) * KC);

#pragma unroll
        for (int ks = 0; ks < 2; ks++) {
            int k0 = ks * 16;
            wmma::fragment<wmma::matrix_a, 16, 16, 16, __nv_bfloat16, wmma::row_major> ah[4], al[4];
            wmma::fragment<wmma::matrix_b, 16, 16, 16, __nv_bfloat16, wmma::col_major> bh[2], bl[2];
#pragma unroll
            for (int mf = 0; mf < 4; mf++)
                wmma::load_matrix_sync(ah[mf], As(buf, 0) + (wr * 64 + mf * 16) * ASTRIDE + k0, ASTRIDE);
#pragma unroll
            for (int nf = 0; nf < 2; nf++)
                wmma::load_matrix_sync(bh[nf], Bs(buf, 0) + (wc * 32 + nf * 16) * ASTRIDE + k0, ASTRIDE);
#pragma unroll
            for (int mf = 0; mf < 4; mf++)
#pragma unroll
                for (int nf = 0; nf < 2; nf++)
                    wmma::mma_sync(acc[mf][nf], ah[mf], bh[nf], acc[mf][nf]);
#pragma unroll
            for (int nf = 0; nf < 2; nf++)
                wmma::load_matrix_sync(bl[nf], Bs(buf, 1) + (wc * 32 + nf * 16) * ASTRIDE + k0, ASTRIDE);
#pragma unroll
            for (int mf = 0; mf < 4; mf++)
#pragma unroll
                for (int nf = 0; nf < 2; nf++)
                    wmma::mma_sync(acc[mf][nf], ah[mf], bl[nf], acc[mf][nf]);
#pragma unroll
            for (int mf = 0; mf < 4; mf++)
                wmma::load_matrix_sync(al[mf], As(buf, 1) + (wr * 64 + mf * 16) * ASTRIDE + k0, ASTRIDE);
#pragma unroll
            for (int mf = 0; mf < 4; mf++)
#pragma unroll
                for (int nf = 0; nf < 2; nf++)
                    wmma::mma_sync(acc[mf][nf], al[mf], bh[nf], acc[mf][nf]);
        }

        __syncthreads();
        if (i + 1 < nk) {
            sstore(buf ^ 1);
            __syncthreads();
        }
    }

    // ---- epilogue: stage fp32 tile in smem, then coalesced writeout ----
    float* Sepi = (float*)sm;          // 128 x 132 fp32 = 67584 B <= 81920
#pragma unroll
    for (int mf = 0; mf < 4; mf++)
#pragma unroll
        for (int nf = 0; nf < 2; nf++)
            wmma::store_matrix_sync(Sepi + (size_t)(wr * 64 + mf * 16) * 132 + wc * 32 + nf * 16,
                                    acc[mf][nf], 132, wmma::mem_row_major);
    __syncthreads();

#pragma unroll
    for (int t = 0; t < 16; t++) {
        int idx = tid + t * 256;        // 0..4095 float4 slots
        int row = idx >> 5;
        int col = (idx & 31) * 4;
        float4 v = *(float4*)&Sepi[(size_t)row * 132 + col];
        float f[4] = {v.x, v.y, v.z, v.w};
        if (bias) {
#pragma unroll
            for (int j = 0; j < 4; j++) f[j] += __ldg(&bias[nBase + col + j]);
        }
        if (OM == 0) {
            *(float4*)&((float*)Cout)[(size_t)(mBase + row) * Nfull + nBase + col] =
                make_float4(f[0], f[1], f[2], f[3]);
        } else {
            __nv_bfloat16 hi[4], lo[4];
#pragma unroll
            for (int j = 0; j < 4; j++) {
                float r = fmaxf(f[j], 0.0f);
                split_store(&hi[j], &lo[j], r);
            }
            __nv_bfloat16* Cb = (__nv_bfloat16*)Cout;
            size_t base = (size_t)(mBase + row) * (size_t)(2 * Nfull);
            *(uint2*)&Cb[base + nBase + col] = *(uint2*)hi;
            *(uint2*)&Cb[base + Nfull + nBase + col] = *(uint2*)lo;
        }
    }
}

// ---------------- weight prep ----------------
__global__ void prep_wt(const float* __restrict__ w, __nv_bfloat16* __restrict__ out,
                        int Kd, int Nd) {
    int i = blockIdx.x * blockDim.x + threadIdx.x;
    if (i >= Kd * Nd) return;
    int k = i / Nd, n = i % Nd;
    split_store(&out[(size_t)n * (2 * Kd) + k], &out[(size_t)n * (2 * Kd) + Kd + k], w[i]);
}
__global__ void prep_wsum(const float* __restrict__ w1) {
    int i = blockIdx.x * blockDim.x + threadIdx.x;
    if (i >= 128 * 1024) return;
    int k = i >> 10, n = i & 1023;
    float v = w1[(size_t)(128 + k) * 1024 + n] + w1[(size_t)(256 + k) * 1024 + n];
    split_store(&g_Wsum[(size_t)n * 256 + k], &g_Wsum[(size_t)n * 256 + 128 + k], v);
}
__global__ void prep_wp(const float* __restrict__ w1) {
    int i = blockIdx.x * blockDim.x + threadIdx.x;
    if (i >= 256 * 1024) return;
    int k = i >> 10, n = i & 1023;
    float v = (k < 128) ? w1[(size_t)k * 1024 + n] : -w1[(size_t)(k + 128) * 1024 + n];
    split_store(&g_WPt[(size_t)n * 512 + k], &g_WPt[(size_t)n * 512 + 256 + k], v);
}

// ---------------- transpose + split ----------------
__global__ void transpose_split(const float* __restrict__ in, __nv_bfloat16* __restrict__ out,
                                int NP, long long inBatch, long long outBatch,
                                int outStride, int hiOff, int loOff) {
    __shared__ float tile[32][33];
    int b = blockIdx.z;
    const float* inb = in + (long long)b * inBatch;
    __nv_bfloat16* outb = out + (long long)b * outBatch;
    int n0 = blockIdx.x * 32, k0 = blockIdx.y * 32;
    int tx = threadIdx.x, ty = threadIdx.y;
    tile[ty][tx] = inb[(long long)(k0 + ty) * NP + n0 + tx];
    __syncthreads();
    float v = tile[tx][ty];
    long long base = (long long)(n0 + ty) * outStride;
    split_store(&outb[base + hiOff + k0 + tx], &outb[base + loOff + k0 + tx], v);
}

// ---------------- per-corner layer-1 assembly (split bf16 out) ----------------
__global__ __launch_bounds__(256)
void assemble_kernel(const float* __restrict__ coord, const float* __restrict__ w1,
                     float vx, float vy) {
    int r = blockIdx.x;
    int b = r >> 16;
    float c0 = coord[(long long)r * 2 + 0];
    float c1 = coord[(long long)r * 2 + 1];
    float cy = c0 + vx * 0.015625f;
    float cx = c1 + vy * 0.015625f;
    float fy = (cy + 1.0f) * 64.0f / 2.0f - 0.5f;
    float fx = (cx + 1.0f) * 64.0f / 2.0f - 0.5f;
    int iy = (int)floorf(fy + 0.5f);
    int ix = (int)floorf(fx + 0.5f);
    bool valid = (iy >= 0 && iy < 64 && ix >= 0 && ix < 64);
    int iyc = min(max(iy, 0), 63);
    int ixc = min(max(ix, 0), 63);
    int t = b * 4096 + iyc * 64 + ixc;
    float ry, rx2;
    if (valid) {
        float cenY = -1.0f + 0.015625f + 0.03125f * (float)iyc;
        float cenX = -1.0f + 0.015625f + 0.03125f * (float)ixc;
        ry  = (c0 - cenY) * 64.0f;
        rx2 = (c1 - cenX) * 64.0f;
    } else {
        ry  = c0 * 64.0f;
        rx2 = c1 * 64.0f;
    }
    float vm = valid ? 1.0f : 0.0f;

    int k = threadIdx.x * 4;
    float4 hp  = *(const float4*)&g_hrproj[(long long)r * 1024 + k];
    float4 pp  = *(const float4*)&g_P[(long long)t * 1024 + k];
    float4 wd0 = *(const float4*)&w1[384 * 1024 + k];
    float4 wd1 = *(const float4*)&w1[385 * 1024 + k];
    float v[4];
    v[0] = fmaxf(hp.x + vm * pp.x + ry * wd0.x + rx2 * wd1.x, 0.0f);
    v[1] = fmaxf(hp.y + vm * pp.y + ry * wd0.y + rx2 * wd1.y, 0.0f);
    v[2] = fmaxf(hp.z + vm * pp.z + ry * wd0.z + rx2 * wd1.z, 0.0f);
    v[3] = fmaxf(hp.w + vm * pp.w + ry * wd0.w + rx2 * wd1.w, 0.0f);
    __nv_bfloat16 hi[4], lo[4];
#pragma unroll
    for (int j = 0; j < 4; j++) split_store(&hi[j], &lo[j], v[j]);
    *(uint2*)&g_act1[(long long)r * 2048 + k] = *(uint2*)hi;
    *(uint2*)&g_act1[(long long)r * 2048 + 1024 + k] = *(uint2*)lo;
}

// ---------------- layer 5 ----------------
__global__ __launch_bounds__(256)
void final5_kernel(const float* __restrict__ w5, const float* __restrict__ b5, int corner) {
    int warp = (blockIdx.x * blockDim.x + threadIdx.x) >> 5;
    int lane = threadIdx.x & 31;
    if (warp >= MROWS) return;
    const __nv_bfloat16* a = &g_act4[(size_t)warp * 256];
    float s0 = 0.0f, s1 = 0.0f;
#pragma unroll
    for (int i = lane; i < 128; i += 32) {
        float av = __bfloat162float(a[i]) + __bfloat162float(a[128 + i]);
        s0 += av * w5[i * 2 + 0];
        s1 += av * w5[i * 2 + 1];
    }
#pragma unroll
    for (int off = 16; off > 0; off >>= 1) {
        s0 += __shfl_xor_sync(0xffffffffu, s0, off);
        s1 += __shfl_xor_sync(0xffffffffu, s1, off);
    }
    if (lane == 0) {
        g_preds[(size_t)warp * 8 + corner * 2 + 0] = s0 + b5[0];
        g_preds[(size_t)warp * 8 + corner * 2 + 1] = s1 + b5[1];
    }
}

// ---------------- softmax blend ----------------
__global__ __launch_bounds__(256)
void reduce_kernel(float* __restrict__ out) {
    int r = blockIdx.x * blockDim.x + threadIdx.x;
    if (r >= MROWS) return;
    float p0[4], p1[4];
#pragma unroll
    for (int c = 0; c < 4; c++) {
        p0[c] = g_preds[(size_t)r * 8 + c * 2 + 0];
        p1[c] = g_preds[(size_t)r * 8 + c * 2 + 1];
    }
    float m = fmaxf(fmaxf(p1[0], p1[1]), fmaxf(p1[2], p1[3]));
    float se = 0.0f, num = 0.0f;
#pragma unroll
    for (int c = 0; c < 4; c++) {
        float e = expf(p1[c] - m);
        se += e;
        num += p0[c] * e;
    }
    out[r] = num / se;
}

// ---------------- launch ----------------
extern "C" void kernel_launch(void* const* d_in, const int* in_sizes, int n_in,
                              void* d_out, int out_size) {
    const float* feat  = (const float*)d_in[0];
    const float* coord = (const float*)d_in[1];
    const float* hrg   = (const float*)d_in[2];
    const float* lrg   = (const float*)d_in[3];
    const float* w1 = (const float*)d_in[4];
    const float* b1 = (const float*)d_in[5];
    const float* w2 = (const float*)d_in[6];
    const float* b2 = (const float*)d_in[7];
    const float* w3 = (const float*)d_in[8];
    const float* b3 = (const float*)d_in[9];
    const float* w4 = (const float*)d_in[10];
    const float* b4 = (const float*)d_in[11];
    const float* w5 = (const float*)d_in[12];
    const float* b5 = (const float*)d_in[13];
    float* out = (float*)d_out;

    __nv_bfloat16 *p_hrT, *p_texT, *p_Wsum, *p_WPt, *p_W2t, *p_W3t, *p_W4t;
    __nv_bfloat16 *p_act1, *p_act2, *p_act3, *p_act4;
    float *p_hrproj, *p_P;
    cudaGetSymbolAddress((void**)&p_hrT, g_hrT);
    cudaGetSymbolAddress((void**)&p_texT, g_texT);
    cudaGetSymbolAddress((void**)&p_Wsum, g_Wsum);
    cudaGetSymbolAddress((void**)&p_WPt, g_WPt);
    cudaGetSymbolAddress((void**)&p_W2t, g_W2t);
    cudaGetSymbolAddress((void**)&p_W3t, g_W3t);
    cudaGetSymbolAddress((void**)&p_W4t, g_W4t);
    cudaGetSymbolAddress((void**)&p_hrproj, g_hrproj);
    cudaGetSymbolAddress((void**)&p_P, g_P);
    cudaGetSymbolAddress((void**)&p_act1, g_act1);
    cudaGetSymbolAddress((void**)&p_act2, g_act2);
    cudaGetSymbolAddress((void**)&p_act3, g_act3);
    cudaGetSymbolAddress((void**)&p_act4, g_act4);

    const int SMB = 2 * (int)STAGEB;   // 81920 bytes
    cudaFuncSetAttribute(gemm_wmma<0>, cudaFuncAttributeMaxDynamicSharedMemorySize, SMB);
    cudaFuncSetAttribute(gemm_wmma<1>, cudaFuncAttributeMaxDynamicSharedMemorySize, SMB);

    // weight prep
    prep_wsum<<<(128 * 1024 + 255) / 256, 256>>>(w1);
    prep_wp<<<(256 * 1024 + 255) / 256, 256>>>(w1);
    prep_wt<<<(1024 * 512 + 255) / 256, 256>>>(w2, p_W2t, 1024, 512);
    prep_wt<<<(512 * 256 + 255) / 256, 256>>>(w3, p_W3t, 512, 256);
    prep_wt<<<(256 * 128 + 255) / 256, 256>>>(w4, p_W4t, 256, 128);

    // transposes + split
    dim3 tb(32, 32);
    transpose_split<<<dim3(65536 / 32, 4, 2), tb>>>(
        hrg, p_hrT, 65536, 128LL * 65536, 65536LL * 256, 256, 0, 128);
    transpose_split<<<dim3(4096 / 32, 4, 2), tb>>>(
        feat, p_texT, 4096, 128LL * 4096, 4096LL * 512, 512, 0, 256);
    transpose_split<<<dim3(4096 / 32, 4, 2), tb>>>(
        lrg, p_texT, 4096, 128LL * 4096, 4096LL * 512, 512, 128, 384);

    // hr_proj = hrT @ Wsum^T + b1      [131072, 1024] fp32
    gemm_wmma<0><<<dim3(8, 1024), 256, SMB>>>(p_hrT, p_Wsum, 128, 1024, b1, p_hrproj);
    // P = texT @ WPt^T                 [8192, 1024] fp32
    gemm_wmma<0><<<dim3(8, 64), 256, SMB>>>(p_texT, p_WPt, 256, 1024, (const float*)0, p_P);

    const float vxs[4] = {-1.0f, -1.0f, 1.0f, 1.0f};
    const float vys[4] = {-1.0f, 1.0f, -1.0f, 1.0f};
    for (int c = 0; c < 4; c++) {
        assemble_kernel<<<MROWS, 256>>>(coord, w1, vxs[c], vys[c]);
        gemm_wmma<1><<<dim3(4, 1024), 256, SMB>>>(p_act1, p_W2t, 1024, 512, b2, p_act2);
        gemm_wmma<1><<<dim3(2, 1024), 256, SMB>>>(p_act2, p_W3t, 512, 256, b3, p_act3);
        gemm_wmma<1><<<dim3(1, 1024), 256, SMB>>>(p_act3, p_W4t, 256, 128, b4, p_act4);
        final5_kernel<<<MROWS / 8, 256>>>(w5, b5, c);
    }
    reduce_kernel<<<MROWS / 256, 256>>>(out);
}

// round 17
// speedup vs baseline: 2.3215x; 1.2744x over previous
#include <cuda_runtime.h>
#include <cuda_bf16.h>
#include <mma.h>
#include <cstdint>
#include <math.h>

using namespace nvcuda;

#define MROWS 131072
#define TTEX  8192
#define KC    32
#define AST   40   // bf16 elems per smem row (32 + 8 pad)

// ---------------- static scratch ----------------
__device__ __align__(256) __nv_bfloat16 g_hrT [(size_t)MROWS * 256];   // [r][hi128|lo128]
__device__ __align__(256) __nv_bfloat16 g_texT[(size_t)TTEX  * 512];   // [t][hi256|lo256]
__device__ __align__(256) __nv_bfloat16 g_Wsum[1024 * 256];
__device__ __align__(256) __nv_bfloat16 g_WPt [1024 * 512];
__device__ __align__(256) __nv_bfloat16 g_W2t [512 * 2048];
__device__ __align__(256) __nv_bfloat16 g_W3t [256 * 1024];
__device__ __align__(256) __nv_bfloat16 g_W4t [128 * 512];
__device__ __align__(256) float g_hrproj[(size_t)MROWS * 1024];
__device__ __align__(256) float g_P     [(size_t)TTEX  * 1024];
__device__ __align__(256) __nv_bfloat16 g_act1[(size_t)MROWS * 2048];
__device__ __align__(256) __nv_bfloat16 g_act2[(size_t)MROWS * 1024];
__device__ __align__(256) __nv_bfloat16 g_act3[(size_t)MROWS * 512];
__device__ float g_preds[(size_t)MROWS * 8];

__device__ __forceinline__ void split_store(__nv_bfloat16* hi, __nv_bfloat16* lo, float v) {
    __nv_bfloat16 h = __float2bfloat16(v);
    *hi = h;
    *lo = __float2bfloat16(v - __bfloat162float(h));
}
__device__ __forceinline__ uint32_t smem_u32(const void* p) {
    uint32_t a;
    asm("{ .reg .u64 t; cvta.to.shared.u64 t, %1; cvt.u32.u64 %0, t; }" : "=r"(a) : "l"(p));
    return a;
}
#define CP_ASYNC16(dst, src) \
    asm volatile("cp.async.cg.shared.global [%0], [%1], 16;" :: "r"(dst), "l"(src) : "memory")
#define CP_COMMIT() asm volatile("cp.async.commit_group;" ::: "memory")
#define CP_WAIT0()  asm volatile("cp.async.wait_group 0;" ::: "memory")

// ================= split-bf16 WMMA GEMM, CTA 128 x NT, warp 64 x NT/4 =================
// A: [M][2K] bf16 (hi|lo), B: [N][2K] bf16 (hi|lo). C = A @ B^T.
// OM=0: fp32 out [M][Nfull]. OM=1: ReLU + split-bf16 out (hi at col, lo at Nfull+col).
// OM=2 (NT=128 only): layer4+final5 fused -> g_preds.
template <int NT, int OM>
__global__ __launch_bounds__(256)
void gemm2(const __nv_bfloat16* __restrict__ A, const __nv_bfloat16* __restrict__ B,
           int K, int Nfull, const float* __restrict__ bias, void* __restrict__ Cout,
           const float* __restrict__ w5, const float* __restrict__ b5, int corner) {
    extern __shared__ char sm[];
    const int tid = threadIdx.x, wid = tid >> 5, lane = tid & 31;
    const int wr = wid >> 2, wc = wid & 3;      // warp tile: rows wr*64, cols wc*WN
    constexpr int WN = NT / 4;
    constexpr int NF = WN / 16;
    const int mBase = blockIdx.y * 128, nBase = blockIdx.x * NT;
    const int ld = 2 * K;
    constexpr int AELE = 128 * AST;             // elems per (buf,comp) A plane
    constexpr int BELE = NT * AST;
    constexpr int AITEMS = 1024;                // 16B items per A chunk
    constexpr int BITEMS = NT * 8;
    const uint32_t sA = smem_u32(sm);
    __nv_bfloat16* smb = (__nv_bfloat16*)sm;

    wmma::fragment<wmma::accumulator, 16, 16, 16, float> acc[4][NF];
#pragma unroll
    for (int mf = 0; mf < 4; mf++)
#pragma unroll
        for (int nf = 0; nf < NF; nf++) wmma::fill_fragment(acc[mf][nf], 0.0f);

    auto fill = [&](int buf, int kc) {
#pragma unroll
        for (int it = tid; it < AITEMS + BITEMS; it += 256) {
            uint32_t dst; const __nv_bfloat16* src;
            if (it < AITEMS) {
                int seg = it & 3, comp = (it >> 2) & 1, row = it >> 3;
                dst = sA + (uint32_t)(buf * 2 + comp) * (AELE * 2) + row * (AST * 2) + seg * 16;
                src = A + (size_t)(mBase + row) * ld + (size_t)comp * K + kc + seg * 8;
            } else {
                int j = it - AITEMS;
                int seg = j & 3, comp = (j >> 2) & 1, row = j >> 3;
                dst = sA + 4u * (AELE * 2) + (uint32_t)(buf * 2 + comp) * (BELE * 2) +
                      row * (AST * 2) + seg * 16;
                src = B + (size_t)(nBase + row) * ld + (size_t)comp * K + kc + seg * 8;
            }
            CP_ASYNC16(dst, src);
        }
    };

    const int nk = K / KC;
    fill(0, 0);
    CP_COMMIT();

    for (int i = 0; i < nk; i++) {
        int buf = i & 1;
        CP_WAIT0();
        __syncthreads();
        if (i + 1 < nk) { fill(buf ^ 1, (i + 1) * KC); CP_COMMIT(); }

        const __nv_bfloat16* Ahi = smb + (size_t)(buf * 2 + 0) * AELE;
        const __nv_bfloat16* Alo = smb + (size_t)(buf * 2 + 1) * AELE;
        const __nv_bfloat16* Bhi = smb + 4 * AELE + (size_t)(buf * 2 + 0) * BELE;
        const __nv_bfloat16* Blo = smb + 4 * AELE + (size_t)(buf * 2 + 1) * BELE;

#pragma unroll
        for (int ks = 0; ks < 2; ks++) {
            int k0 = ks * 16;
            wmma::fragment<wmma::matrix_a, 16, 16, 16, __nv_bfloat16, wmma::row_major> ah[4], al[4];
            wmma::fragment<wmma::matrix_b, 16, 16, 16, __nv_bfloat16, wmma::col_major> bh[NF], bl[NF];
#pragma unroll
            for (int mf = 0; mf < 4; mf++)
                wmma::load_matrix_sync(ah[mf], Ahi + (wr * 64 + mf * 16) * AST + k0, AST);
#pragma unroll
            for (int nf = 0; nf < NF; nf++)
                wmma::load_matrix_sync(bh[nf], Bhi + (wc * WN + nf * 16) * AST + k0, AST);
#pragma unroll
            for (int mf = 0; mf < 4; mf++)
#pragma unroll
                for (int nf = 0; nf < NF; nf++)
                    wmma::mma_sync(acc[mf][nf], ah[mf], bh[nf], acc[mf][nf]);
#pragma unroll
            for (int nf = 0; nf < NF; nf++)
                wmma::load_matrix_sync(bl[nf], Blo + (wc * WN + nf * 16) * AST + k0, AST);
#pragma unroll
            for (int mf = 0; mf < 4; mf++)
#pragma unroll
                for (int nf = 0; nf < NF; nf++)
                    wmma::mma_sync(acc[mf][nf], ah[mf], bl[nf], acc[mf][nf]);
#pragma unroll
            for (int mf = 0; mf < 4; mf++)
                wmma::load_matrix_sync(al[mf], Alo + (wr * 64 + mf * 16) * AST + k0, AST);
#pragma unroll
            for (int mf = 0; mf < 4; mf++)
#pragma unroll
                for (int nf = 0; nf < NF; nf++)
                    wmma::mma_sync(acc[mf][nf], al[mf], bh[nf], acc[mf][nf]);
        }
    }
    __syncthreads();

    // ---- epilogue ----
    float* Sepi = (float*)sm;   // 128 x 132 fp32 staging (67584 B)
#pragma unroll
    for (int p = 0; p < NT / 128; p++) {
        if (p) __syncthreads();
        if (NT == 128 || (wc >> 1) == p) {
            int cbase = (NT == 128) ? wc * WN : (wc & 1) * 64;
#pragma unroll
            for (int mf = 0; mf < 4; mf++)
#pragma unroll
                for (int nf = 0; nf < NF; nf++)
                    wmma::store_matrix_sync(Sepi + (size_t)(wr * 64 + mf * 16) * 132 + cbase + nf * 16,
                                            acc[mf][nf], 132, wmma::mem_row_major);
        }
        __syncthreads();

        if (OM == 2) {
            // fused layer5: per-row dots with w5 (128x2) after bias+relu
#pragma unroll
            for (int rr = 0; rr < 16; rr++) {
                int row = wid * 16 + rr;
                float s0 = 0.0f, s1 = 0.0f;
#pragma unroll
                for (int cc = lane; cc < 128; cc += 32) {
                    float av = fmaxf(Sepi[(size_t)row * 132 + cc] + __ldg(&bias[cc]), 0.0f);
                    float2 wv = *(const float2*)&w5[cc * 2];
                    s0 += av * wv.x;
                    s1 += av * wv.y;
                }
#pragma unroll
                for (int off = 16; off > 0; off >>= 1) {
                    s0 += __shfl_xor_sync(0xffffffffu, s0, off);
                    s1 += __shfl_xor_sync(0xffffffffu, s1, off);
                }
                if (lane == 0) {
                    g_preds[(size_t)(mBase + row) * 8 + corner * 2 + 0] = s0 + __ldg(&b5[0]);
                    g_preds[(size_t)(mBase + row) * 8 + corner * 2 + 1] = s1 + __ldg(&b5[1]);
                }
            }
        } else {
#pragma unroll
            for (int w = 0; w < 16; w++) {
                int idx = tid + w * 256;
                int row = idx >> 5, col = (idx & 31) * 4;
                float4 v = *(float4*)&Sepi[(size_t)row * 132 + col];
                int gcol = nBase + p * 128 + col;
                float f[4] = {v.x, v.y, v.z, v.w};
                if (bias) {
#pragma unroll
                    for (int j = 0; j < 4; j++) f[j] += __ldg(&bias[gcol + j]);
                }
                if (OM == 0) {
                    *(float4*)&((float*)Cout)[(size_t)(mBase + row) * Nfull + gcol] =
                        make_float4(f[0], f[1], f[2], f[3]);
                } else {
                    __nv_bfloat16 hi[4], lo[4];
#pragma unroll
                    for (int j = 0; j < 4; j++) {
                        float r = fmaxf(f[j], 0.0f);
                        split_store(&hi[j], &lo[j], r);
                    }
                    __nv_bfloat16* Cb = (__nv_bfloat16*)Cout;
                    size_t base = (size_t)(mBase + row) * (size_t)(2 * Nfull);
                    *(uint2*)&Cb[base + gcol] = *(uint2*)hi;
                    *(uint2*)&Cb[base + Nfull + gcol] = *(uint2*)lo;
                }
            }
        }
    }
}

// ---------------- weight prep ----------------
__global__ void prep_wt(const float* __restrict__ w, __nv_bfloat16* __restrict__ out,
                        int Kd, int Nd) {
    int i = blockIdx.x * blockDim.x + threadIdx.x;
    if (i >= Kd * Nd) return;
    int k = i / Nd, n = i % Nd;
    split_store(&out[(size_t)n * (2 * Kd) + k], &out[(size_t)n * (2 * Kd) + Kd + k], w[i]);
}
__global__ void prep_wsum(const float* __restrict__ w1) {
    int i = blockIdx.x * blockDim.x + threadIdx.x;
    if (i >= 128 * 1024) return;
    int k = i >> 10, n = i & 1023;
    float v = w1[(size_t)(128 + k) * 1024 + n] + w1[(size_t)(256 + k) * 1024 + n];
    split_store(&g_Wsum[(size_t)n * 256 + k], &g_Wsum[(size_t)n * 256 + 128 + k], v);
}
__global__ void prep_wp(const float* __restrict__ w1) {
    int i = blockIdx.x * blockDim.x + threadIdx.x;
    if (i >= 256 * 1024) return;
    int k = i >> 10, n = i & 1023;
    float v = (k < 128) ? w1[(size_t)k * 1024 + n] : -w1[(size_t)(k + 128) * 1024 + n];
    split_store(&g_WPt[(size_t)n * 512 + k], &g_WPt[(size_t)n * 512 + 256 + k], v);
}

// ---------------- transpose + split ----------------
__global__ void transpose_split(const float* __restrict__ in, __nv_bfloat16* __restrict__ out,
                                int NP, long long inBatch, long long outBatch,
                                int outStride, int hiOff, int loOff) {
    __shared__ float tile[32][33];
    int b = blockIdx.z;
    const float* inb = in + (long long)b * inBatch;
    __nv_bfloat16* outb = out + (long long)b * outBatch;
    int n0 = blockIdx.x * 32, k0 = blockIdx.y * 32;
    int tx = threadIdx.x, ty = threadIdx.y;
    tile[ty][tx] = inb[(long long)(k0 + ty) * NP + n0 + tx];
    __syncthreads();
    float v = tile[tx][ty];
    long long base = (long long)(n0 + ty) * outStride;
    split_store(&outb[base + hiOff + k0 + tx], &outb[base + loOff + k0 + tx], v);
}

// ---------------- per-corner layer-1 assembly (split bf16 out) ----------------
__global__ __launch_bounds__(256)
void assemble_kernel(const float* __restrict__ coord, const float* __restrict__ w1,
                     float vx, float vy) {
    int r = blockIdx.x;
    int b = r >> 16;
    float c0 = coord[(long long)r * 2 + 0];
    float c1 = coord[(long long)r * 2 + 1];
    float cy = c0 + vx * 0.015625f;
    float cx = c1 + vy * 0.015625f;
    float fy = (cy + 1.0f) * 64.0f / 2.0f - 0.5f;
    float fx = (cx + 1.0f) * 64.0f / 2.0f - 0.5f;
    int iy = (int)floorf(fy + 0.5f);
    int ix = (int)floorf(fx + 0.5f);
    bool valid = (iy >= 0 && iy < 64 && ix >= 0 && ix < 64);
    int iyc = min(max(iy, 0), 63);
    int ixc = min(max(ix, 0), 63);
    int t = b * 4096 + iyc * 64 + ixc;
    float ry, rx2;
    if (valid) {
        float cenY = -1.0f + 0.015625f + 0.03125f * (float)iyc;
        float cenX = -1.0f + 0.015625f + 0.03125f * (float)ixc;
        ry  = (c0 - cenY) * 64.0f;
        rx2 = (c1 - cenX) * 64.0f;
    } else {
        ry  = c0 * 64.0f;
        rx2 = c1 * 64.0f;
    }
    float vm = valid ? 1.0f : 0.0f;

    int k = threadIdx.x * 4;
    float4 hp  = *(const float4*)&g_hrproj[(long long)r * 1024 + k];
    float4 pp  = *(const float4*)&g_P[(long long)t * 1024 + k];
    float4 wd0 = *(const float4*)&w1[384 * 1024 + k];
    float4 wd1 = *(const float4*)&w1[385 * 1024 + k];
    float v[4];
    v[0] = fmaxf(hp.x + vm * pp.x + ry * wd0.x + rx2 * wd1.x, 0.0f);
    v[1] = fmaxf(hp.y + vm * pp.y + ry * wd0.y + rx2 * wd1.y, 0.0f);
    v[2] = fmaxf(hp.z + vm * pp.z + ry * wd0.z + rx2 * wd1.z, 0.0f);
    v[3] = fmaxf(hp.w + vm * pp.w + ry * wd0.w + rx2 * wd1.w, 0.0f);
    __nv_bfloat16 hi[4], lo[4];
#pragma unroll
    for (int j = 0; j < 4; j++) split_store(&hi[j], &lo[j], v[j]);
    *(uint2*)&g_act1[(long long)r * 2048 + k] = *(uint2*)hi;
    *(uint2*)&g_act1[(long long)r * 2048 + 1024 + k] = *(uint2*)lo;
}

// ---------------- softmax blend ----------------
__global__ __launch_bounds__(256)
void reduce_kernel(float* __restrict__ out) {
    int r = blockIdx.x * blockDim.x + threadIdx.x;
    if (r >= MROWS) return;
    float p0[4], p1[4];
#pragma unroll
    for (int c = 0; c < 4; c++) {
        p0[c] = g_preds[(size_t)r * 8 + c * 2 + 0];
        p1[c] = g_preds[(size_t)r * 8 + c * 2 + 1];
    }
    float m = fmaxf(fmaxf(p1[0], p1[1]), fmaxf(p1[2], p1[3]));
    float se = 0.0f, num = 0.0f;
#pragma unroll
    for (int c = 0; c < 4; c++) {
        float e = expf(p1[c] - m);
        se += e;
        num += p0[c] * e;
    }
    out[r] = num / se;
}

// ---------------- launch ----------------
extern "C" void kernel_launch(void* const* d_in, const int* in_sizes, int n_in,
                              void* d_out, int out_size) {
    const float* feat  = (const float*)d_in[0];
    const float* coord = (const float*)d_in[1];
    const float* hrg   = (const float*)d_in[2];
    const float* lrg   = (const float*)d_in[3];
    const float* w1 = (const float*)d_in[4];
    const float* b1 = (const float*)d_in[5];
    const float* w2 = (const float*)d_in[6];
    const float* b2 = (const float*)d_in[7];
    const float* w3 = (const float*)d_in[8];
    const float* b3 = (const float*)d_in[9];
    const float* w4 = (const float*)d_in[10];
    const float* b4 = (const float*)d_in[11];
    const float* w5 = (const float*)d_in[12];
    const float* b5 = (const float*)d_in[13];
    float* out = (float*)d_out;

    __nv_bfloat16 *p_hrT, *p_texT, *p_Wsum, *p_WPt, *p_W2t, *p_W3t, *p_W4t;
    __nv_bfloat16 *p_act1, *p_act2, *p_act3;
    float *p_hrproj, *p_P;
    cudaGetSymbolAddress((void**)&p_hrT, g_hrT);
    cudaGetSymbolAddress((void**)&p_texT, g_texT);
    cudaGetSymbolAddress((void**)&p_Wsum, g_Wsum);
    cudaGetSymbolAddress((void**)&p_WPt, g_WPt);
    cudaGetSymbolAddress((void**)&p_W2t, g_W2t);
    cudaGetSymbolAddress((void**)&p_W3t, g_W3t);
    cudaGetSymbolAddress((void**)&p_W4t, g_W4t);
    cudaGetSymbolAddress((void**)&p_hrproj, g_hrproj);
    cudaGetSymbolAddress((void**)&p_P, g_P);
    cudaGetSymbolAddress((void**)&p_act1, g_act1);
    cudaGetSymbolAddress((void**)&p_act2, g_act2);
    cudaGetSymbolAddress((void**)&p_act3, g_act3);

    const int SMB256 = (4 * 128 + 4 * 256) * AST * 2;   // 122880
    const int SMB128 = (4 * 128 + 4 * 128) * AST * 2;   // 81920
    cudaFuncSetAttribute(gemm2<256, 0>, cudaFuncAttributeMaxDynamicSharedMemorySize, SMB256);
    cudaFuncSetAttribute(gemm2<256, 1>, cudaFuncAttributeMaxDynamicSharedMemorySize, SMB256);
    cudaFuncSetAttribute(gemm2<128, 2>, cudaFuncAttributeMaxDynamicSharedMemorySize, SMB128);

    // weight prep
    prep_wsum<<<(128 * 1024 + 255) / 256, 256>>>(w1);
    prep_wp<<<(256 * 1024 + 255) / 256, 256>>>(w1);
    prep_wt<<<(1024 * 512 + 255) / 256, 256>>>(w2, p_W2t, 1024, 512);
    prep_wt<<<(512 * 256 + 255) / 256, 256>>>(w3, p_W3t, 512, 256);
    prep_wt<<<(256 * 128 + 255) / 256, 256>>>(w4, p_W4t, 256, 128);

    // transposes + split
    dim3 tb(32, 32);
    transpose_split<<<dim3(65536 / 32, 4, 2), tb>>>(
        hrg, p_hrT, 65536, 128LL * 65536, 65536LL * 256, 256, 0, 128);
    transpose_split<<<dim3(4096 / 32, 4, 2), tb>>>(
        feat, p_texT, 4096, 128LL * 4096, 4096LL * 512, 512, 0, 256);
    transpose_split<<<dim3(4096 / 32, 4, 2), tb>>>(
        lrg, p_texT, 4096, 128LL * 4096, 4096LL * 512, 512, 128, 384);

    // hr_proj = hrT @ Wsum^T + b1      [131072, 1024] fp32
    gemm2<256, 0><<<dim3(4, 1024), 256, SMB256>>>(p_hrT, p_Wsum, 128, 1024, b1, p_hrproj,
                                                  (const float*)0, (const float*)0, 0);
    // P = texT @ WPt^T                 [8192, 1024] fp32
    gemm2<256, 0><<<dim3(4, 64), 256, SMB256>>>(p_texT, p_WPt, 256, 1024, (const float*)0, p_P,
                                                (const float*)0, (const float*)0, 0);

    const float vxs[4] = {-1.0f, -1.0f, 1.0f, 1.0f};
    const float vys[4] = {-1.0f, 1.0f, -1.0f, 1.0f};
    for (int c = 0; c < 4; c++) {
        assemble_kernel<<<MROWS, 256>>>(coord, w1, vxs[c], vys[c]);
        gemm2<256, 1><<<dim3(2, 1024), 256, SMB256>>>(p_act1, p_W2t, 1024, 512, b2, p_act2,
                                                      (const float*)0, (const float*)0, 0);
        gemm2<256, 1><<<dim3(1, 1024), 256, SMB256>>>(p_act2, p_W3t, 512, 256, b3, p_act3,
                                                      (const float*)0, (const float*)0, 0);
        gemm2<128, 2><<<dim3(1, 1024), 256, SMB128>>>(p_act3, p_W4t, 256, 128, b4, (void*)0,
                                                      w5, b5, c);
    }
    reduce_kernel<<<MROWS / 256, 256>>>(out);
}